// round 14
// baseline (speedup 1.0000x reference)
#include <cuda_runtime.h>
#include <cstdint>

#define DD       256
#define M_TILE   128
#define KC       32
#define NCHUNK   24
#define NSTAGE   4
#define NTHREADS 1024
#define LRELU    0.01f
#define LN_EPS   1e-5f

// ---- smem layout (bytes) ----
#define A_STRIDE    36                              // floats per A row (32 + 4 pad)
#define A_BYTES     (M_TILE * A_STRIDE * 4)         // 18432
#define B_BYTES     (DD * KC * 4)                   // 32768
#define STAGE_BYTES (A_BYTES + B_BYTES)             // 51200
#define SM_HT       (NSTAGE * STAGE_BYTES)          // 204800
#define SM_BIAS     (SM_HT + M_TILE * 8)            // 205824
#define SM_GAMMA    (SM_BIAS + 1024)
#define SM_BETA     (SM_GAMMA + 1024)
#define SM_STAT     (SM_BETA + 1024)                // float2 stat[128][8]
#define SMEM_TOTAL  (SM_STAT + 8192)                // 217088

// W image: 24 chunks x 256 n x 32 k, k-permuted within 16-groups, tf32-rounded
__device__ float g_Wt[NCHUNK * DD * KC];

// ---------------- helpers ----------------
__device__ __forceinline__ uint32_t smem_u32(const void* p) {
    uint32_t a;
    asm("{ .reg .u64 t; cvta.to.shared.u64 t, %1; cvt.u32.u64 %0, t; }" : "=r"(a) : "l"(p));
    return a;
}
__device__ __forceinline__ void cp_async16(uint32_t saddr, const void* gptr) {
    asm volatile("cp.async.cg.shared.global [%0], [%1], 16;" :: "r"(saddr), "l"(gptr));
}
#define CP_COMMIT() asm volatile("cp.async.commit_group;" ::: "memory")
#define CP_WAIT2()  asm volatile("cp.async.wait_group 2;" ::: "memory")

__device__ __forceinline__ uint32_t f2tf(float f) {
    uint32_t u;
    asm("cvt.rna.tf32.f32 %0, %1;" : "=r"(u) : "f"(f));
    return u;
}
__device__ __forceinline__ void mma_tf32(float* d, const uint32_t* a, uint32_t b0, uint32_t b1) {
    asm volatile(
        "mma.sync.aligned.m16n8k8.row.col.f32.tf32.tf32.f32 "
        "{%0,%1,%2,%3}, {%4,%5,%6,%7}, {%8,%9}, {%0,%1,%2,%3};"
        : "+f"(d[0]), "+f"(d[1]), "+f"(d[2]), "+f"(d[3])
        : "r"(a[0]), "r"(a[1]), "r"(a[2]), "r"(a[3]), "r"(b0), "r"(b1));
}

// ---------------- prep: W [768,256] -> permuted, tf32-rounded chunk images ----------------
__global__ __launch_bounds__(256, 4) void prep_W(const float* __restrict__ W) {
    int idx = blockIdx.x * 256 + threadIdx.x;   // 0 .. 196607
    int c = idx >> 13;                          // chunk 0..23
    int r = idx & 8191;
    int n = r >> 5;                             // 0..255
    int k = r & 31;                             // 0..31
    float v = W[(c * KC + k) * DD + n];
    int pos = (k >> 4) * 16 + (k & 3) * 4 + ((k & 15) >> 2);
    g_Wt[c * (DD * KC) + n * KC + pos] = __uint_as_float(f2tf(v));
}

// ---------------- main fused kernel ----------------
// 1024 threads, 32 warps. Warp tile 32 rows x 32 cols:
//   rowg = wid>>3 (0..3) -> rows rowg*32 .. +31 ; coln = wid&7 -> cols coln*32 .. +31
__global__ __launch_bounds__(NTHREADS, 1)
void edge_mma(const float* __restrict__ H, const float* __restrict__ E,
              const int* __restrict__ ht, const float* __restrict__ bias,
              const float* __restrict__ gamma, const float* __restrict__ beta,
              float* __restrict__ out, int M)
{
    extern __shared__ char smem[];
    const uint32_t sb = smem_u32(smem);
    const int tid  = threadIdx.x;
    const int lane = tid & 31;
    const int wid  = tid >> 5;
    const int rowg = wid >> 3;          // 0..3 : rows rowg*32..+31
    const int coln = wid & 7;           // 0..7 : cols coln*32..+31
    const int base = blockIdx.x * M_TILE;

    // stage ht + params
    if (tid < M_TILE) {
        int e = base + tid; if (e >= M) e = M - 1;
        ((int2*)(smem + SM_HT))[tid] = ((const int2*)ht)[e];
    }
    if (tid < DD) {
        ((float*)(smem + SM_BIAS))[tid]  = bias[tid];
        ((float*)(smem + SM_GAMMA))[tid] = gamma[tid];
        ((float*)(smem + SM_BETA))[tid]  = beta[tid];
    }
    __syncthreads();

    auto load_chunk = [&](int c, int s) {
        const uint32_t abase = sb + s * STAGE_BYTES;
        const uint32_t bbase = abase + A_BYTES;
        const int seg  = c >> 3;                 // 0 head, 1 E, 2 tail
        const int koff = (c & 7) * KC;
        // A: 128 rows x 32 floats, stride 36; ONE float4 per thread
        {
            int r = tid >> 3;
            const float* src;
            if (seg == 1) {
                int e = base + r; if (e >= M) e = M - 1;
                src = E + (size_t)e * DD;
            } else {
                int2 p = ((const int2*)(smem + SM_HT))[r];
                src = H + (size_t)(seg == 0 ? p.x : p.y) * DD;
            }
            const int q = tid & 7;
            cp_async16(abase + r * (A_STRIDE * 4) + q * 16, src + koff + q * 4);
        }
        // B: 256 n-rows x 128B, XOR-swizzled; TWO float4 per thread
        {
            const int n = tid >> 2;
            const float* wsrc = g_Wt + (size_t)c * (DD * KC) + n * KC;
            const uint32_t drow = bbase + n * 128;
            const uint32_t sw = (n & 1) << 2;
            const int q0 = (tid & 3) * 2;
#pragma unroll
            for (int i = 0; i < 2; i++) {
                int q = q0 + i;
                cp_async16(drow + ((uint32_t)q ^ sw) * 16, wsrc + q * 4);
            }
        }
    };

    float acc[2][4][4];     // [m][nf][frag]
#pragma unroll
    for (int m = 0; m < 2; m++)
#pragma unroll
        for (int nf = 0; nf < 4; nf++)
#pragma unroll
            for (int q = 0; q < 4; q++) acc[m][nf][q] = 0.f;

    for (int c = 0; c < 3; c++) { load_chunk(c, c); CP_COMMIT(); }

    const int nbase = coln * 32 + (lane >> 2);

#pragma unroll 1
    for (int c = 0; c < NCHUNK; c++) {
        const int s = c & (NSTAGE - 1);
        CP_WAIT2();                              // chunk c resident
        __syncthreads();                         // readers of stage (c+3)%4 (iter c-1) done

        const float* As = (const float*)(smem + s * STAGE_BYTES);
        const char*  Bs = smem + s * STAGE_BYTES + A_BYTES;

#pragma unroll
        for (int g = 0; g < 2; g++) {
            // A fragments for this g (two 16-row m-groups)
            uint32_t ua[2][2][4];
#pragma unroll
            for (int m = 0; m < 2; m++) {
                const int r0 = rowg * 32 + m * 16 + (lane >> 2);
#pragma unroll
                for (int jj = 0; jj < 2; jj++) {
                    const int k = g * 16 + jj * 8 + (lane & 3);
                    ua[m][jj][0] = f2tf(As[r0 * A_STRIDE + k]);
                    ua[m][jj][1] = f2tf(As[(r0 + 8) * A_STRIDE + k]);
                    ua[m][jj][2] = f2tf(As[r0 * A_STRIDE + k + 4]);
                    ua[m][jj][3] = f2tf(As[(r0 + 8) * A_STRIDE + k + 4]);
                }
            }
            // 2-deep B fragment pipeline over 4 nf
            const uint32_t ubase = (uint32_t)(g * 4 + (lane & 3));
            float4 bv_cur, bv_nxt;
            {
                const int n0 = nbase;
                bv_cur = *(const float4*)(Bs + n0 * 128 + ((ubase ^ (uint32_t)((n0 & 1) << 2)) * 16));
            }
#pragma unroll
            for (int nf = 0; nf < 4; nf++) {
                if (nf < 3) {
                    const int n1 = nbase + (nf + 1) * 8;
                    bv_nxt = *(const float4*)(Bs + n1 * 128 + ((ubase ^ (uint32_t)((n1 & 1) << 2)) * 16));
                }
                uint32_t b0 = __float_as_uint(bv_cur.x), b1 = __float_as_uint(bv_cur.y);
                uint32_t b2 = __float_as_uint(bv_cur.z), b3 = __float_as_uint(bv_cur.w);
                mma_tf32(acc[0][nf], ua[0][0], b0, b1);
                mma_tf32(acc[1][nf], ua[1][0], b0, b1);
                mma_tf32(acc[0][nf], ua[0][1], b2, b3);
                mma_tf32(acc[1][nf], ua[1][1], b2, b3);
                bv_cur = bv_nxt;
            }
            // bury the next-chunk load between the two g blocks (R9-proven)
            if (g == 0) {
                if (c + 3 < NCHUNK) load_chunk(c + 3, (c + 3) & (NSTAGE - 1));
                CP_COMMIT();
            }
        }
    }

    // ---------------- epilogue ----------------
    const float* bs = (const float*)(smem + SM_BIAS);
    const float* gs = (const float*)(smem + SM_GAMMA);
    const float* es = (const float*)(smem + SM_BETA);

    int   erows[4];
    const float* erow[4];
    bool  valid[4];
#pragma unroll
    for (int sl = 0; sl < 4; sl++) {            // sl = m*2 + h
        int e = base + rowg * 32 + (sl >> 1) * 16 + (sl & 1) * 8 + (lane >> 2);
        valid[sl] = (e < M);
        erows[sl] = e;
        erow[sl] = E + (size_t)(valid[sl] ? e : (M - 1)) * DD;
    }

    float sum[4] = {0,0,0,0}, sq[4] = {0,0,0,0};
#pragma unroll
    for (int nf = 0; nf < 4; nf++) {
        const int col = coln * 32 + nf * 8 + (lane & 3) * 2;
        float2 bb = *(const float2*)(bs + col);
#pragma unroll
        for (int m = 0; m < 2; m++)
#pragma unroll
            for (int h = 0; h < 2; h++) {
                const int sl = m * 2 + h;
                float2 ev = *(const float2*)(erow[sl] + col);
                float p0 = acc[m][nf][h * 2]     + bb.x; p0 = (p0 >= 0.f) ? p0 : LRELU * p0;
                float p1 = acc[m][nf][h * 2 + 1] + bb.y; p1 = (p1 >= 0.f) ? p1 : LRELU * p1;
                float x0 = p0 + ev.x, x1 = p1 + ev.y;
                sum[sl] += x0 + x1;
                sq[sl]  += x0 * x0 + x1 * x1;
            }
    }
#pragma unroll
    for (int off = 1; off <= 2; off <<= 1)
#pragma unroll
        for (int sl = 0; sl < 4; sl++) {
            sum[sl] += __shfl_xor_sync(0xffffffffu, sum[sl], off);
            sq[sl]  += __shfl_xor_sync(0xffffffffu, sq[sl],  off);
        }
    float2* stat = (float2*)(smem + SM_STAT);
    if ((lane & 3) == 0) {
#pragma unroll
        for (int sl = 0; sl < 4; sl++) {
            int rl = rowg * 32 + (sl >> 1) * 16 + (sl & 1) * 8 + (lane >> 2);
            stat[rl * 8 + coln] = make_float2(sum[sl], sq[sl]);
        }
    }
    __syncthreads();

    float mu[4], inv[4];
#pragma unroll
    for (int sl = 0; sl < 4; sl++) {
        int rl = rowg * 32 + (sl >> 1) * 16 + (sl & 1) * 8 + (lane >> 2);
        float s_ = 0.f, q_ = 0.f;
#pragma unroll
        for (int cq = 0; cq < 8; cq++) {
            float2 t = stat[rl * 8 + cq];
            s_ += t.x; q_ += t.y;
        }
        float m_ = s_ * (1.f / DD);
        float v_ = q_ * (1.f / DD) - m_ * m_;
        mu[sl]  = m_;
        inv[sl] = rsqrtf(v_ + LN_EPS);
    }

#pragma unroll
    for (int nf = 0; nf < 4; nf++) {
        const int col = coln * 32 + nf * 8 + (lane & 3) * 2;
        float2 bb = *(const float2*)(bs + col);
        float2 gg = *(const float2*)(gs + col);
        float2 tb = *(const float2*)(es + col);
#pragma unroll
        for (int m = 0; m < 2; m++)
#pragma unroll
            for (int h = 0; h < 2; h++) {
                const int sl = m * 2 + h;
                if (!valid[sl]) continue;
                float2 ev = *(const float2*)(erow[sl] + col);
                float p0 = acc[m][nf][h * 2]     + bb.x; p0 = (p0 >= 0.f) ? p0 : LRELU * p0;
                float p1 = acc[m][nf][h * 2 + 1] + bb.y; p1 = (p1 >= 0.f) ? p1 : LRELU * p1;
                float x0 = p0 + ev.x, x1 = p1 + ev.y;
                float y0 = gg.x * (x0 - mu[sl]) * inv[sl] + tb.x;
                float y1 = gg.y * (x1 - mu[sl]) * inv[sl] + tb.y;
                *(float2*)(out + (size_t)erows[sl] * DD + col) = make_float2(y0, y1);
            }
    }
}

extern "C" void kernel_launch(void* const* d_in, const int* in_sizes, int n_in,
                              void* d_out, int out_size)
{
    const float* H  = (const float*)d_in[0];
    const float* E  = (const float*)d_in[1];
    const int*   ht = (const int*)d_in[2];
    const float* W  = (const float*)d_in[3];
    const float* b  = (const float*)d_in[4];
    const float* g  = (const float*)d_in[5];
    const float* be = (const float*)d_in[6];
    float*       o  = (float*)d_out;

    const int M = in_sizes[1] / DD;

    cudaFuncSetAttribute(edge_mma, cudaFuncAttributeMaxDynamicSharedMemorySize, SMEM_TOTAL);

    prep_W<<<NCHUNK * DD * KC / 256, 256>>>(W);
    const int grid = (M + M_TILE - 1) / M_TILE;
    edge_mma<<<grid, NTHREADS, SMEM_TOTAL>>>(H, E, ht, b, g, be, o, M);
}

// round 15
// speedup vs baseline: 1.1411x; 1.1411x over previous
#include <cuda_runtime.h>
#include <cstdint>

#define DD       256
#define M_TILE   128
#define KC       32
#define NCHUNK   24
#define NSTAGE   4
#define NTHREADS 512
#define LRELU    0.01f
#define LN_EPS   1e-5f

// ---- smem layout (bytes) ----
#define A_STRIDE    36                              // floats per A row (32 + 4 pad)
#define A_BYTES     (M_TILE * A_STRIDE * 4)         // 18432
#define B_BYTES     (DD * KC * 4)                   // 32768
#define STAGE_BYTES (A_BYTES + B_BYTES)             // 51200
#define SM_HT       (NSTAGE * STAGE_BYTES)          // 204800
#define SM_BIAS     (SM_HT + M_TILE * 8)
#define SM_GAMMA    (SM_BIAS + 1024)
#define SM_BETA     (SM_GAMMA + 1024)
#define SM_STAT     (SM_BETA + 1024)                // float2 stat[128][2]
#define SMEM_TOTAL  (SM_STAT + 2048)                // 210944

// W image: 24 chunks x 256 n x 32 k, k-permuted within 16-groups, tf32-rounded
__device__ float g_Wt[NCHUNK * DD * KC];

// ---------------- helpers ----------------
__device__ __forceinline__ uint32_t smem_u32(const void* p) {
    uint32_t a;
    asm("{ .reg .u64 t; cvta.to.shared.u64 t, %1; cvt.u32.u64 %0, t; }" : "=r"(a) : "l"(p));
    return a;
}
__device__ __forceinline__ void cp_async16(uint32_t saddr, const void* gptr) {
    asm volatile("cp.async.cg.shared.global [%0], [%1], 16;" :: "r"(saddr), "l"(gptr));
}
#define CP_COMMIT() asm volatile("cp.async.commit_group;" ::: "memory")
#define CP_WAIT2()  asm volatile("cp.async.wait_group 2;" ::: "memory")

__device__ __forceinline__ uint32_t f2tf(float f) {
    uint32_t u;
    asm("cvt.rna.tf32.f32 %0, %1;" : "=r"(u) : "f"(f));
    return u;
}
__device__ __forceinline__ void mma_tf32(float* d, const uint32_t* a, uint32_t b0, uint32_t b1) {
    asm volatile(
        "mma.sync.aligned.m16n8k8.row.col.f32.tf32.tf32.f32 "
        "{%0,%1,%2,%3}, {%4,%5,%6,%7}, {%8,%9}, {%0,%1,%2,%3};"
        : "+f"(d[0]), "+f"(d[1]), "+f"(d[2]), "+f"(d[3])
        : "r"(a[0]), "r"(a[1]), "r"(a[2]), "r"(a[3]), "r"(b0), "r"(b1));
}

// ---------------- prep: W [768,256] -> permuted, tf32-rounded chunk images ----------------
__global__ __launch_bounds__(256, 4) void prep_W(const float* __restrict__ W) {
    int idx = blockIdx.x * 256 + threadIdx.x;   // 0 .. 196607
    int c = idx >> 13;                          // chunk 0..23
    int r = idx & 8191;
    int n = r >> 5;                             // 0..255
    int k = r & 31;                             // 0..31
    float v = W[(c * KC + k) * DD + n];
    int pos = (k >> 4) * 16 + (k & 3) * 4 + ((k & 15) >> 2);
    g_Wt[c * (DD * KC) + n * KC + pos] = __uint_as_float(f2tf(v));
}

// ---------------- main fused kernel ----------------
// 512 threads, 16 warps. Warp tile 16 rows x 128 cols:
//   rowg = wid>>1 (0..7) -> rows rowg*16 .. +15 ; colh = wid&1 -> cols colh*128 .. +127
__global__ __launch_bounds__(NTHREADS, 1)
void edge_mma(const float* __restrict__ H, const float* __restrict__ E,
              const int* __restrict__ ht, const float* __restrict__ bias,
              const float* __restrict__ gamma, const float* __restrict__ beta,
              float* __restrict__ out, int M)
{
    extern __shared__ char smem[];
    const uint32_t sb = smem_u32(smem);
    const int tid  = threadIdx.x;
    const int lane = tid & 31;
    const int wid  = tid >> 5;
    const int rowg = wid >> 1;          // 0..7 : rows rowg*16..+15
    const int colh = wid & 1;           // 0..1 : cols colh*128..+127
    const int base = blockIdx.x * M_TILE;

    // stage ht + params
    if (tid < M_TILE) {
        int e = base + tid; if (e >= M) e = M - 1;
        ((int2*)(smem + SM_HT))[tid] = ((const int2*)ht)[e];
    }
    if (tid < DD) {
        ((float*)(smem + SM_BIAS))[tid]  = bias[tid];
        ((float*)(smem + SM_GAMMA))[tid] = gamma[tid];
        ((float*)(smem + SM_BETA))[tid]  = beta[tid];
    }
    __syncthreads();

    auto load_chunk = [&](int c, int s) {
        const uint32_t abase = sb + s * STAGE_BYTES;
        const uint32_t bbase = abase + A_BYTES;
        const int seg  = c >> 3;                 // 0 head, 1 E, 2 tail
        const int koff = (c & 7) * KC;
        // A: 128 rows x 32 floats, stride 36; 2 float4 per thread
        {
            int r = tid >> 2;
            const float* src;
            if (seg == 1) {
                int e = base + r; if (e >= M) e = M - 1;
                src = E + (size_t)e * DD;
            } else {
                int2 p = ((const int2*)(smem + SM_HT))[r];
                src = H + (size_t)(seg == 0 ? p.x : p.y) * DD;
            }
            src += koff;
            const int q0 = (tid & 3) * 2;
#pragma unroll
            for (int i = 0; i < 2; i++) {
                int q = q0 + i;
                cp_async16(abase + r * (A_STRIDE * 4) + q * 16, src + q * 4);
            }
        }
        // B: 256 n-rows x 128B, XOR-swizzled 16B units; 4 float4 per thread
        {
            const int n = tid >> 1;
            const float* wsrc = g_Wt + (size_t)c * (DD * KC) + n * KC;
            const uint32_t drow = bbase + n * 128;
            const uint32_t sw = (n & 1) << 2;
            const int q0 = (tid & 1) * 4;
#pragma unroll
            for (int i = 0; i < 4; i++) {
                int q = q0 + i;
                cp_async16(drow + ((uint32_t)q ^ sw) * 16, wsrc + q * 4);
            }
        }
    };

    float acc[16][4];       // [nf][frag] : 16 nf x 8 cols = 128 cols
#pragma unroll
    for (int nf = 0; nf < 16; nf++)
#pragma unroll
        for (int q = 0; q < 4; q++) acc[nf][q] = 0.f;

    for (int c = 0; c < 3; c++) { load_chunk(c, c); CP_COMMIT(); }

    const int nbase = colh * 128 + (lane >> 2);

#pragma unroll 1
    for (int c = 0; c < NCHUNK; c++) {
        const int s = c & (NSTAGE - 1);
        CP_WAIT2();                              // chunk c resident
        __syncthreads();                         // readers of stage (c+3)%4 (iter c-1) done

        const float* As = (const float*)(smem + s * STAGE_BYTES);
        const char*  Bs = smem + s * STAGE_BYTES + A_BYTES;

#pragma unroll
        for (int g = 0; g < 2; g++) {
            // A fragments for this g (single 16-row m-group): 8 LDS + 8 cvt
            uint32_t ua[2][4];
            {
                const int r0 = rowg * 16 + (lane >> 2);
#pragma unroll
                for (int jj = 0; jj < 2; jj++) {
                    const int k = g * 16 + jj * 8 + (lane & 3);
                    ua[jj][0] = f2tf(As[r0 * A_STRIDE + k]);
                    ua[jj][1] = f2tf(As[(r0 + 8) * A_STRIDE + k]);
                    ua[jj][2] = f2tf(As[r0 * A_STRIDE + k + 4]);
                    ua[jj][3] = f2tf(As[(r0 + 8) * A_STRIDE + k + 4]);
                }
            }
            // nf-pair pipeline: 2-deep over pairs, acc chain distance 2
            const uint32_t ubase = (uint32_t)(g * 4 + (lane & 3));
            float4 bva, bvb, bva_n, bvb_n;
            {
                const int n0 = nbase;
                const int n1 = nbase + 8;
                bva = *(const float4*)(Bs + n0 * 128 + ((ubase ^ (uint32_t)((n0 & 1) << 2)) * 16));
                bvb = *(const float4*)(Bs + n1 * 128 + ((ubase ^ (uint32_t)((n1 & 1) << 2)) * 16));
            }
#pragma unroll
            for (int np = 0; np < 8; np++) {     // pair (2np, 2np+1)
                if (np < 7) {
                    const int n0 = nbase + (2 * np + 2) * 8;
                    const int n1 = nbase + (2 * np + 3) * 8;
                    bva_n = *(const float4*)(Bs + n0 * 128 + ((ubase ^ (uint32_t)((n0 & 1) << 2)) * 16));
                    bvb_n = *(const float4*)(Bs + n1 * 128 + ((ubase ^ (uint32_t)((n1 & 1) << 2)) * 16));
                }
                uint32_t a0 = __float_as_uint(bva.x), a1 = __float_as_uint(bva.y);
                uint32_t a2 = __float_as_uint(bva.z), a3 = __float_as_uint(bva.w);
                uint32_t c0 = __float_as_uint(bvb.x), c1 = __float_as_uint(bvb.y);
                uint32_t c2 = __float_as_uint(bvb.z), c3 = __float_as_uint(bvb.w);
                mma_tf32(acc[2 * np],     ua[0], a0, a1);
                mma_tf32(acc[2 * np + 1], ua[0], c0, c1);
                mma_tf32(acc[2 * np],     ua[1], a2, a3);
                mma_tf32(acc[2 * np + 1], ua[1], c2, c3);
                bva = bva_n; bvb = bvb_n;
            }
            // bury the next-chunk load between the two g blocks (R9-proven)
            if (g == 0) {
                if (c + 3 < NCHUNK) load_chunk(c + 3, (c + 3) & (NSTAGE - 1));
                CP_COMMIT();
            }
        }
    }

    // ---------------- epilogue ----------------
    const float* bs = (const float*)(smem + SM_BIAS);
    const float* gs = (const float*)(smem + SM_GAMMA);
    const float* es = (const float*)(smem + SM_BETA);

    int   erows[2];
    const float* erow[2];
    bool  valid[2];
#pragma unroll
    for (int sl = 0; sl < 2; sl++) {
        int e = base + rowg * 16 + sl * 8 + (lane >> 2);
        valid[sl] = (e < M);
        erows[sl] = e;
        erow[sl] = E + (size_t)(valid[sl] ? e : (M - 1)) * DD;
    }

    float sum[2] = {0,0}, sq[2] = {0,0};
#pragma unroll
    for (int nf = 0; nf < 16; nf++) {
        const int col = colh * 128 + nf * 8 + (lane & 3) * 2;
        float2 bb = *(const float2*)(bs + col);
#pragma unroll
        for (int sl = 0; sl < 2; sl++) {
            float2 ev = *(const float2*)(erow[sl] + col);
            float p0 = acc[nf][sl * 2]     + bb.x; p0 = (p0 >= 0.f) ? p0 : LRELU * p0;
            float p1 = acc[nf][sl * 2 + 1] + bb.y; p1 = (p1 >= 0.f) ? p1 : LRELU * p1;
            float x0 = p0 + ev.x, x1 = p1 + ev.y;
            sum[sl] += x0 + x1;
            sq[sl]  += x0 * x0 + x1 * x1;
        }
    }
#pragma unroll
    for (int off = 1; off <= 2; off <<= 1)
#pragma unroll
        for (int sl = 0; sl < 2; sl++) {
            sum[sl] += __shfl_xor_sync(0xffffffffu, sum[sl], off);
            sq[sl]  += __shfl_xor_sync(0xffffffffu, sq[sl],  off);
        }
    float2* stat = (float2*)(smem + SM_STAT);
    if ((lane & 3) == 0) {
#pragma unroll
        for (int sl = 0; sl < 2; sl++) {
            int rl = rowg * 16 + sl * 8 + (lane >> 2);
            stat[rl * 2 + colh] = make_float2(sum[sl], sq[sl]);
        }
    }
    __syncthreads();

    float mu[2], inv[2];
#pragma unroll
    for (int sl = 0; sl < 2; sl++) {
        int rl = rowg * 16 + sl * 8 + (lane >> 2);
        float2 t0 = stat[rl * 2 + 0];
        float2 t1 = stat[rl * 2 + 1];
        float m_ = (t0.x + t1.x) * (1.f / DD);
        float v_ = (t0.y + t1.y) * (1.f / DD) - m_ * m_;
        mu[sl]  = m_;
        inv[sl] = rsqrtf(v_ + LN_EPS);
    }

#pragma unroll
    for (int nf = 0; nf < 16; nf++) {
        const int col = colh * 128 + nf * 8 + (lane & 3) * 2;
        float2 bb = *(const float2*)(bs + col);
        float2 gg = *(const float2*)(gs + col);
        float2 tb = *(const float2*)(es + col);
#pragma unroll
        for (int sl = 0; sl < 2; sl++) {
            if (!valid[sl]) continue;
            float2 ev = *(const float2*)(erow[sl] + col);
            float p0 = acc[nf][sl * 2]     + bb.x; p0 = (p0 >= 0.f) ? p0 : LRELU * p0;
            float p1 = acc[nf][sl * 2 + 1] + bb.y; p1 = (p1 >= 0.f) ? p1 : LRELU * p1;
            float x0 = p0 + ev.x, x1 = p1 + ev.y;
            float y0 = gg.x * (x0 - mu[sl]) * inv[sl] + tb.x;
            float y1 = gg.y * (x1 - mu[sl]) * inv[sl] + tb.y;
            *(float2*)(out + (size_t)erows[sl] * DD + col) = make_float2(y0, y1);
        }
    }
}

extern "C" void kernel_launch(void* const* d_in, const int* in_sizes, int n_in,
                              void* d_out, int out_size)
{
    const float* H  = (const float*)d_in[0];
    const float* E  = (const float*)d_in[1];
    const int*   ht = (const int*)d_in[2];
    const float* W  = (const float*)d_in[3];
    const float* b  = (const float*)d_in[4];
    const float* g  = (const float*)d_in[5];
    const float* be = (const float*)d_in[6];
    float*       o  = (float*)d_out;

    const int M = in_sizes[1] / DD;

    cudaFuncSetAttribute(edge_mma, cudaFuncAttributeMaxDynamicSharedMemorySize, SMEM_TOTAL);

    prep_W<<<NCHUNK * DD * KC / 256, 256>>>(W);
    const int grid = (M + M_TILE - 1) / M_TILE;
    edge_mma<<<grid, NTHREADS, SMEM_TOTAL>>>(H, E, ht, b, g, be, o, M);
}

// round 16
// speedup vs baseline: 1.3243x; 1.1606x over previous
#include <cuda_runtime.h>
#include <cstdint>

#define DD       256
#define M_TILE   128
#define KC       32
#define NCHUNK   24
#define NSTAGE   4
#define NTHREADS 512
#define LRELU    0.01f
#define LN_EPS   1e-5f

// ---- smem layout (bytes) ----
#define A_STRIDE    36                              // floats per A row (32 + 4 pad)
#define A_BYTES     (M_TILE * A_STRIDE * 4)         // 18432
#define B_BYTES     (DD * KC * 4)                   // 32768
#define STAGE_BYTES (A_BYTES + B_BYTES)             // 51200
#define SM_HT       (NSTAGE * STAGE_BYTES)          // 204800
#define SM_BIAS     (SM_HT + M_TILE * 8)
#define SM_GAMMA    (SM_BIAS + 1024)
#define SM_BETA     (SM_GAMMA + 1024)
#define SM_STAT     (SM_BETA + 1024)
#define SMEM_TOTAL  (SM_STAT + 4096)                // 212992

// W image: 24 chunks x 256 n x 32 k, k-permuted within 16-groups, tf32-rounded
__device__ float g_Wt[NCHUNK * DD * KC];

// ---------------- helpers ----------------
__device__ __forceinline__ uint32_t smem_u32(const void* p) {
    uint32_t a;
    asm("{ .reg .u64 t; cvta.to.shared.u64 t, %1; cvt.u32.u64 %0, t; }" : "=r"(a) : "l"(p));
    return a;
}
__device__ __forceinline__ void cp_async16(uint32_t saddr, const void* gptr) {
    asm volatile("cp.async.cg.shared.global [%0], [%1], 16;" :: "r"(saddr), "l"(gptr));
}
#define CP_COMMIT() asm volatile("cp.async.commit_group;" ::: "memory")
#define CP_WAIT2()  asm volatile("cp.async.wait_group 2;" ::: "memory")

__device__ __forceinline__ uint32_t f2tf(float f) {
    uint32_t u;
    asm("cvt.rna.tf32.f32 %0, %1;" : "=r"(u) : "f"(f));
    return u;
}
__device__ __forceinline__ void ldsm_x4(uint32_t* r, uint32_t saddr) {
    asm volatile("ldmatrix.sync.aligned.m8n8.x4.shared.b16 {%0,%1,%2,%3}, [%4];"
        : "=r"(r[0]), "=r"(r[1]), "=r"(r[2]), "=r"(r[3]) : "r"(saddr));
}
__device__ __forceinline__ void mma_tf32(float* d, const uint32_t* a, uint32_t b0, uint32_t b1) {
    asm volatile(
        "mma.sync.aligned.m16n8k8.row.col.f32.tf32.tf32.f32 "
        "{%0,%1,%2,%3}, {%4,%5,%6,%7}, {%8,%9}, {%0,%1,%2,%3};"
        : "+f"(d[0]), "+f"(d[1]), "+f"(d[2]), "+f"(d[3])
        : "r"(a[0]), "r"(a[1]), "r"(a[2]), "r"(a[3]), "r"(b0), "r"(b1));
}

// ---------------- prep: W [768,256] -> permuted, tf32-rounded chunk images ----------------
__global__ __launch_bounds__(256, 4) void prep_W(const float* __restrict__ W) {
    int idx = blockIdx.x * 256 + threadIdx.x;   // 0 .. 196607
    int c = idx >> 13;                          // chunk 0..23
    int r = idx & 8191;
    int n = r >> 5;                             // 0..255
    int k = r & 31;                             // 0..31
    float v = W[(c * KC + k) * DD + n];
    int pos = (k >> 4) * 16 + (k & 3) * 4 + ((k & 15) >> 2);
    g_Wt[c * (DD * KC) + n * KC + pos] = __uint_as_float(f2tf(v));
}

// ---------------- main fused kernel ----------------
__global__ __launch_bounds__(NTHREADS, 1)
void edge_mma(const float* __restrict__ H, const float* __restrict__ E,
              const int* __restrict__ ht, const float* __restrict__ bias,
              const float* __restrict__ gamma, const float* __restrict__ beta,
              float* __restrict__ out, int M)
{
    extern __shared__ char smem[];
    const uint32_t sb = smem_u32(smem);
    const int tid  = threadIdx.x;
    const int lane = tid & 31;
    const int wid  = tid >> 5;
    const int rowg = wid >> 2;          // 0..3 : rows rowg*32..+31
    const int colq = wid & 3;           // 0..3 : cols colq*64..+63
    const int base = blockIdx.x * M_TILE;

    // stage ht + params
    if (tid < M_TILE) {
        int e = base + tid; if (e >= M) e = M - 1;
        ((int2*)(smem + SM_HT))[tid] = ((const int2*)ht)[e];
    }
    if (tid < DD) {
        ((float*)(smem + SM_BIAS))[tid]  = bias[tid];
        ((float*)(smem + SM_GAMMA))[tid] = gamma[tid];
        ((float*)(smem + SM_BETA))[tid]  = beta[tid];
    }
    __syncthreads();

    auto load_chunk = [&](int c, int s) {
        const uint32_t abase = sb + s * STAGE_BYTES;
        const uint32_t bbase = abase + A_BYTES;
        const int seg  = c >> 3;                 // 0 head, 1 E, 2 tail
        const int koff = (c & 7) * KC;
        // A: 128 rows x 32 floats, row stride 36 floats; 2 float4 per thread
        {
            int r = tid >> 2;
            const float* src;
            if (seg == 1) {
                int e = base + r; if (e >= M) e = M - 1;
                src = E + (size_t)e * DD;
            } else {
                int2 p = ((const int2*)(smem + SM_HT))[r];
                src = H + (size_t)(seg == 0 ? p.x : p.y) * DD;
            }
            src += koff;
            const int q0 = (tid & 3) * 2;
#pragma unroll
            for (int i = 0; i < 2; i++) {
                int q = q0 + i;
                cp_async16(abase + r * (A_STRIDE * 4) + q * 16, src + q * 4);
            }
        }
        // B: 256 n-rows x 128B, XOR-swizzled 16B units; 4 float4 per thread
        {
            const int n = tid >> 1;
            const float* wsrc = g_Wt + (size_t)c * (DD * KC) + n * KC;
            const uint32_t drow = bbase + n * 128;
            const uint32_t sw = (n & 1) << 2;
            const int q0 = (tid & 1) * 4;
#pragma unroll
            for (int i = 0; i < 4; i++) {
                int q = q0 + i;
                cp_async16(drow + ((uint32_t)q ^ sw) * 16, wsrc + q * 4);
            }
        }
    };

    float acc[2][8][4];
#pragma unroll
    for (int m = 0; m < 2; m++)
#pragma unroll
        for (int nf = 0; nf < 8; nf++)
#pragma unroll
            for (int q = 0; q < 4; q++) acc[m][nf][q] = 0.f;

    for (int c = 0; c < 3; c++) { load_chunk(c, c); CP_COMMIT(); }

    const int nbase = colq * 64 + (lane >> 2);
    // ldmatrix per-lane address base: lanes 0-15 -> rows 0-15 (k bytes +0),
    // lanes 16-31 -> rows 0-15 (k bytes +16)
    const int rowLocal = (lane < 16) ? lane : (lane - 16);
    const uint32_t kextra = (lane < 16) ? 0u : 16u;
    const uint32_t a_lane_base = (uint32_t)((rowg * 32 + rowLocal) * (A_STRIDE * 4)) + kextra;

#pragma unroll 1
    for (int c = 0; c < NCHUNK; c++) {
        const int s = c & (NSTAGE - 1);
        CP_WAIT2();                              // chunk c resident
        __syncthreads();                         // readers of stage (c+3)%4 (iter c-1) done

        const uint32_t a_stage = sb + s * STAGE_BYTES + a_lane_base;
        const char*    Bs = smem + s * STAGE_BYTES + A_BYTES;

#pragma unroll
        for (int g = 0; g < 2; g++) {
            // A fragments via ldmatrix.x4: one per (m, jj)
            uint32_t ua[2][2][4];
#pragma unroll
            for (int m = 0; m < 2; m++)
#pragma unroll
                for (int jj = 0; jj < 2; jj++)
                    ldsm_x4(ua[m][jj],
                            a_stage + (uint32_t)(m * 16 * (A_STRIDE * 4) + g * 64 + jj * 32));
            // tf32 round all fragments (batched: good MLP)
#pragma unroll
            for (int m = 0; m < 2; m++)
#pragma unroll
                for (int jj = 0; jj < 2; jj++)
#pragma unroll
                    for (int q = 0; q < 4; q++)
                        ua[m][jj][q] = f2tf(__uint_as_float(ua[m][jj][q]));

            // 2-deep B fragment pipeline
            const uint32_t ubase = (uint32_t)(g * 4 + (lane & 3));
            float4 bv_cur, bv_nxt;
            {
                const int n0 = nbase;
                bv_cur = *(const float4*)(Bs + n0 * 128 + ((ubase ^ (uint32_t)((n0 & 1) << 2)) * 16));
            }
#pragma unroll
            for (int nf = 0; nf < 8; nf++) {
                if (nf < 7) {
                    const int n1 = nbase + (nf + 1) * 8;
                    bv_nxt = *(const float4*)(Bs + n1 * 128 + ((ubase ^ (uint32_t)((n1 & 1) << 2)) * 16));
                }
                uint32_t b0 = __float_as_uint(bv_cur.x), b1 = __float_as_uint(bv_cur.y);
                uint32_t b2 = __float_as_uint(bv_cur.z), b3 = __float_as_uint(bv_cur.w);
                mma_tf32(acc[0][nf], ua[0][0], b0, b1);
                mma_tf32(acc[1][nf], ua[1][0], b0, b1);
                mma_tf32(acc[0][nf], ua[0][1], b2, b3);
                mma_tf32(acc[1][nf], ua[1][1], b2, b3);
                bv_cur = bv_nxt;
            }
            // bury the next-chunk load between the two g blocks (R9-proven)
            if (g == 0) {
                if (c + 3 < NCHUNK) load_chunk(c + 3, (c + 3) & (NSTAGE - 1));
                CP_COMMIT();
            }
        }
    }

    // ---------------- epilogue ----------------
    const float* bs = (const float*)(smem + SM_BIAS);
    const float* gs = (const float*)(smem + SM_GAMMA);
    const float* es = (const float*)(smem + SM_BETA);

    int   erows[4];
    const float* erow[4];
    bool  valid[4];
#pragma unroll
    for (int sl = 0; sl < 4; sl++) {
        int e = base + rowg * 32 + sl * 8 + (lane >> 2);
        valid[sl] = (e < M);
        erows[sl] = e;
        erow[sl] = E + (size_t)(valid[sl] ? e : (M - 1)) * DD;
    }

    float sum[4] = {0,0,0,0}, sq[4] = {0,0,0,0};
#pragma unroll
    for (int nf = 0; nf < 8; nf++) {
        const int col = colq * 64 + nf * 8 + (lane & 3) * 2;
        float2 bb = *(const float2*)(bs + col);
#pragma unroll
        for (int m = 0; m < 2; m++)
#pragma unroll
            for (int h = 0; h < 2; h++) {
                const int sl = m * 2 + h;
                float2 ev = *(const float2*)(erow[sl] + col);
                float p0 = acc[m][nf][h * 2]     + bb.x; p0 = (p0 >= 0.f) ? p0 : LRELU * p0;
                float p1 = acc[m][nf][h * 2 + 1] + bb.y; p1 = (p1 >= 0.f) ? p1 : LRELU * p1;
                float x0 = p0 + ev.x, x1 = p1 + ev.y;
                sum[sl] += x0 + x1;
                sq[sl]  += x0 * x0 + x1 * x1;
            }
    }
#pragma unroll
    for (int off = 1; off <= 2; off <<= 1)
#pragma unroll
        for (int sl = 0; sl < 4; sl++) {
            sum[sl] += __shfl_xor_sync(0xffffffffu, sum[sl], off);
            sq[sl]  += __shfl_xor_sync(0xffffffffu, sq[sl],  off);
        }
    float2* stat = (float2*)(smem + SM_STAT);
    if ((lane & 3) == 0) {
#pragma unroll
        for (int sl = 0; sl < 4; sl++) {
            int rl = rowg * 32 + sl * 8 + (lane >> 2);
            stat[rl * 4 + colq] = make_float2(sum[sl], sq[sl]);
        }
    }
    __syncthreads();

    float mu[4], inv[4];
#pragma unroll
    for (int sl = 0; sl < 4; sl++) {
        int rl = rowg * 32 + sl * 8 + (lane >> 2);
        float s_ = 0.f, q_ = 0.f;
#pragma unroll
        for (int cq = 0; cq < 4; cq++) {
            float2 t = stat[rl * 4 + cq];
            s_ += t.x; q_ += t.y;
        }
        float m_ = s_ * (1.f / DD);
        float v_ = q_ * (1.f / DD) - m_ * m_;
        mu[sl]  = m_;
        inv[sl] = rsqrtf(v_ + LN_EPS);
    }

#pragma unroll
    for (int nf = 0; nf < 8; nf++) {
        const int col = colq * 64 + nf * 8 + (lane & 3) * 2;
        float2 bb = *(const float2*)(bs + col);
        float2 gg = *(const float2*)(gs + col);
        float2 tb = *(const float2*)(es + col);
#pragma unroll
        for (int m = 0; m < 2; m++)
#pragma unroll
            for (int h = 0; h < 2; h++) {
                const int sl = m * 2 + h;
                if (!valid[sl]) continue;
                float2 ev = *(const float2*)(erow[sl] + col);
                float p0 = acc[m][nf][h * 2]     + bb.x; p0 = (p0 >= 0.f) ? p0 : LRELU * p0;
                float p1 = acc[m][nf][h * 2 + 1] + bb.y; p1 = (p1 >= 0.f) ? p1 : LRELU * p1;
                float x0 = p0 + ev.x, x1 = p1 + ev.y;
                float y0 = gg.x * (x0 - mu[sl]) * inv[sl] + tb.x;
                float y1 = gg.y * (x1 - mu[sl]) * inv[sl] + tb.y;
                *(float2*)(out + (size_t)erows[sl] * DD + col) = make_float2(y0, y1);
            }
    }
}

extern "C" void kernel_launch(void* const* d_in, const int* in_sizes, int n_in,
                              void* d_out, int out_size)
{
    const float* H  = (const float*)d_in[0];
    const float* E  = (const float*)d_in[1];
    const int*   ht = (const int*)d_in[2];
    const float* W  = (const float*)d_in[3];
    const float* b  = (const float*)d_in[4];
    const float* g  = (const float*)d_in[5];
    const float* be = (const float*)d_in[6];
    float*       o  = (float*)d_out;

    const int M = in_sizes[1] / DD;

    cudaFuncSetAttribute(edge_mma, cudaFuncAttributeMaxDynamicSharedMemorySize, SMEM_TOTAL);

    prep_W<<<NCHUNK * DD * KC / 256, 256>>>(W);
    const int grid = (M + M_TILE - 1) / M_TILE;
    edge_mma<<<grid, NTHREADS, SMEM_TOTAL>>>(H, E, ht, b, g, be, o, M);
}